// round 16
// baseline (speedup 1.0000x reference)
#include <cuda_runtime.h>
#include <cuda_fp16.h>
#include <cstdint>

#define Bb 2
#define Ll 32768
#define Cc 128
#define NTOK 512
#define HD 32

// ---- smem byte offsets (per 256-thread CTA) ----
#define KF_OFF  0           // K fp16: 512 rows x 64B (swizzled)      32768
#define VH_OFF  32768       // V fp16 row-major: 512 rows x 80B       40960
#define OS_OFF  73728       // O fp32 [256][36] staging (also Q fp16 stage pre-mainloop)
#define QS_OFF  OS_OFF      //   Q fp16: 256 rows x 64B (swizzled)
#define WS_OFF  110592      // weights [27][32] f32                    3456
#define BS_OFF  114048      // bias [32] f32                            128
#define SMEM_BYTES 114176   // x2 CTAs/SM = 228352 <= 228KB

static __device__ __forceinline__ uint32_t s2u(const void* p){
    uint32_t a;
    asm("{ .reg .u64 t; cvta.to.shared.u64 t, %1; cvt.u32.u64 %0, t; }" : "=r"(a) : "l"(p));
    return a;
}
static __device__ __forceinline__ uint32_t pk2h(float a, float b){
    uint32_t r; asm("cvt.rn.f16x2.f32 %0, %1, %2;" : "=r"(r) : "f"(b), "f"(a)); return r;
}
static __device__ __forceinline__ uint32_t ex2h2(uint32_t a){
    uint32_t r; asm("ex2.approx.f16x2 %0, %1;" : "=r"(r) : "r"(a)); return r;
}
static __device__ __forceinline__ uint32_t hadd2(uint32_t a, uint32_t b){
    uint32_t r; asm("add.f16x2 %0, %1, %2;" : "=r"(r) : "r"(a), "r"(b)); return r;
}
static __device__ __forceinline__ float h2sum(uint32_t w){
    const __half2 h = *reinterpret_cast<const __half2*>(&w);
    const float2 f = __half22float2(h);
    return f.x + f.y;
}
static __device__ __forceinline__ void ldm4(uint32_t* r, uint32_t a){
    asm volatile("ldmatrix.sync.aligned.m8n8.x4.shared.b16 {%0,%1,%2,%3}, [%4];"
        : "=r"(r[0]), "=r"(r[1]), "=r"(r[2]), "=r"(r[3]) : "r"(a));
}
static __device__ __forceinline__ void ldm4t(uint32_t* r, uint32_t a){
    asm volatile("ldmatrix.sync.aligned.m8n8.x4.trans.shared.b16 {%0,%1,%2,%3}, [%4];"
        : "=r"(r[0]), "=r"(r[1]), "=r"(r[2]), "=r"(r[3]) : "r"(a));
}
static __device__ __forceinline__ void mma16816(float* d, const uint32_t* a, uint32_t b0, uint32_t b1){
    asm volatile("mma.sync.aligned.m16n8k16.row.col.f32.f16.f16.f32 "
        "{%0,%1,%2,%3},{%4,%5,%6,%7},{%8,%9},{%0,%1,%2,%3};"
        : "+f"(d[0]), "+f"(d[1]), "+f"(d[2]), "+f"(d[3])
        : "r"(a[0]), "r"(a[1]), "r"(a[2]), "r"(a[3]), "r"(b0), "r"(b1));
}
static __device__ __forceinline__ void sts_v4(uint32_t a, uint32_t x, uint32_t y, uint32_t z, uint32_t w){
    asm volatile("st.shared.v4.b32 [%0], {%1,%2,%3,%4};" :: "r"(a), "r"(x), "r"(y), "r"(z), "r"(w) : "memory");
}
static __device__ __forceinline__ void lds_v4(uint32_t* r, uint32_t a){
    asm volatile("ld.shared.v4.b32 {%0,%1,%2,%3}, [%4];"
        : "=r"(r[0]), "=r"(r[1]), "=r"(r[2]), "=r"(r[3]) : "r"(a));
}
// 64B rows; 16B-chunk c rotated by (row>>1) -> conflict-free ldmatrix (used for K and Q)
static __device__ __forceinline__ uint32_t kaddr(int n, int c){
    return (uint32_t)n*64u + ((((uint32_t)c + ((uint32_t)n >> 1)) & 3u) * 16u);
}

__global__ void __launch_bounds__(256, 2)
lepe_hmma(const float* __restrict__ qkv,
          const float* __restrict__ lw,
          const float* __restrict__ lb,
          float* __restrict__ out)
{
    extern __shared__ char sm[];
    const uint32_t smb = s2u(sm);
    const int tid = threadIdx.x;
    const int wid = tid >> 5, lane = tid & 31;

    const int bx = blockIdx.x;            // (window, head, qhalf)
    const int win = bx >> 3, head = (bx >> 1) & 3, qhalf = bx & 1;
    const int b  = win >> 6;
    const int tB = (win >> 4) & 3;
    const int wB = win & 15;
    const size_t batch_off = (size_t)b * Ll * Cc;
    const int chan  = head * HD;
    const int lbase = tB*8192 + wB*4;

    const float* qg = qkv + batch_off;
    const float* kg = qkv + (size_t)1*Bb*Ll*Cc + batch_off;
    const float* vg = qkv + (size_t)2*Bb*Ll*Cc + batch_off;

    // ---------- stage K fp16 (swizzled), V fp16 row-major, Q fp16 (swizzled, scaled) ----------
    {
        const int q = tid & 3;            // 4 threads per row, 8 d-values each
        const int rbase = tid >> 2;       // 0..63
        #pragma unroll
        for (int it = 0; it < 8; it++){
            const int j = it*64 + rbase;
            const int t = j >> 8, h = (j >> 2) & 63, ws = j & 3;
            const size_t l = (size_t)(lbase + t*4096 + h*64 + ws);
            const float4 k0 = *(const float4*)(kg + l*Cc + chan + q*8);
            const float4 k1 = *(const float4*)(kg + l*Cc + chan + q*8 + 4);
            sts_v4(smb + KF_OFF + kaddr(j, q),
                   pk2h(k0.x, k0.y), pk2h(k0.z, k0.w),
                   pk2h(k1.x, k1.y), pk2h(k1.z, k1.w));

            const float4 v0 = *(const float4*)(vg + l*Cc + chan + q*8);
            const float4 v1 = *(const float4*)(vg + l*Cc + chan + q*8 + 4);
            sts_v4(smb + VH_OFF + (uint32_t)j*80u + (uint32_t)q*16u,
                   pk2h(v0.x, v0.y), pk2h(v0.z, v0.w),
                   pk2h(v1.x, v1.y), pk2h(v1.z, v1.w));
        }
        // Q: 256 local rows (this qhalf), scaled into log2 domain
        const float sc = 0.17677669529663689f * 1.4426950408889634f;
        #pragma unroll
        for (int it = 0; it < 4; it++){
            const int rl = it*64 + rbase;                 // local q-row 0..255
            const int r  = qhalf*256 + rl;                // global in-window row
            const int t = r >> 8, h = (r >> 2) & 63, ws = r & 3;
            const size_t l = (size_t)(lbase + t*4096 + h*64 + ws);
            const float4 q0 = *(const float4*)(qg + l*Cc + chan + q*8);
            const float4 q1 = *(const float4*)(qg + l*Cc + chan + q*8 + 4);
            sts_v4(smb + QS_OFF + kaddr(rl, q),
                   pk2h(q0.x*sc, q0.y*sc), pk2h(q0.z*sc, q0.w*sc),
                   pk2h(q1.x*sc, q1.y*sc), pk2h(q1.z*sc, q1.w*sc));
        }
        for (int idx = tid; idx < 27*32; idx += 256){
            const int tap = idx >> 5, d = idx & 31;
            ((float*)(sm + WS_OFF))[tap*32 + d] = lw[(chan + d)*27 + tap];
        }
        if (tid < 32) ((float*)(sm + BS_OFF))[tid] = lb[chan + tid];
    }
    __syncthreads();

    // ---------- Q fragments via ldmatrix from smem ----------
    const int qbl = wid*32;               // local (within-CTA) row base for this warp
    uint32_t qf[2][2][4];
    {
        const int row_off = (lane & 7) + ((lane >> 3) & 1)*8;
        const int ch_base = (lane >> 4);  // 0 or 1
        #pragma unroll
        for (int mt = 0; mt < 2; mt++)
            #pragma unroll
            for (int kt = 0; kt < 2; kt++)
                ldm4(qf[mt][kt], smb + QS_OFF + kaddr(qbl + mt*16 + row_off, ch_base + kt*2));
    }

    // ---------- mainloop: 32 subchunks of 16 keys (16 MMAs/warp-iter = shape floor) ----------
    float oAcc[2][4][4];
    #pragma unroll
    for (int a = 0; a < 2; a++)
        #pragma unroll
        for (int b2 = 0; b2 < 4; b2++)
            #pragma unroll
            for (int c = 0; c < 4; c++) oAcc[a][b2][c] = 0.f;
    float rs[2][2] = {{0.f,0.f},{0.f,0.f}};   // per-thread partial row sums (mt, row-half)

    const int lg = lane >> 3, lr = lane & 7;

    #pragma unroll 1
    for (int cs = 0; cs < 32; cs++){
        const int j0 = cs * 16;
        // K fragments (B operand for QK)
        uint32_t kh[2][4];
        #pragma unroll
        for (int nt = 0; nt < 2; nt++)
            ldm4(kh[nt], smb + KF_OFF + kaddr(j0 + nt*8 + lr, lg));
        // V fragments via ldmatrix.trans from row-major fp16 V
        uint32_t vh[2][4];
        #pragma unroll
        for (int dg = 0; dg < 2; dg++){
            const uint32_t a = smb + VH_OFF
                + (uint32_t)(j0 + (lg & 1)*8 + lr)*80u
                + (uint32_t)dg*32u + (uint32_t)(lg >> 1)*16u;
            ldm4t(vh[dg], a);
        }
        // S = Q K^T (single fp16 term)
        float s[2][2][4];
        #pragma unroll
        for (int mt = 0; mt < 2; mt++)
            #pragma unroll
            for (int nt = 0; nt < 2; nt++){
                float* sd = s[mt][nt];
                sd[0]=sd[1]=sd[2]=sd[3]=0.f;
                mma16816(sd, qf[mt][0], kh[nt][0], kh[nt][1]);
                mma16816(sd, qf[mt][1], kh[nt][2], kh[nt][3]);
            }
        // softmax in f16x2 + ALU row-sum partials + PV
        #pragma unroll
        for (int mt = 0; mt < 2; mt++){
            uint32_t ah[4];
            ah[0] = ex2h2(pk2h(s[mt][0][0], s[mt][0][1]));   // row r,   cols 2c,2c+1
            ah[1] = ex2h2(pk2h(s[mt][0][2], s[mt][0][3]));   // row r+8, cols 2c,2c+1
            ah[2] = ex2h2(pk2h(s[mt][1][0], s[mt][1][1]));   // row r,   cols 8+2c,..
            ah[3] = ex2h2(pk2h(s[mt][1][2], s[mt][1][3]));   // row r+8, cols 8+2c,..
            rs[mt][0] += h2sum(hadd2(ah[0], ah[2]));         // row r partial
            rs[mt][1] += h2sum(hadd2(ah[1], ah[3]));         // row r+8 partial
            #pragma unroll
            for (int ntd = 0; ntd < 4; ntd++){
                const int dg = ntd >> 1;
                mma16816(oAcc[mt][ntd], ah, vh[dg][(ntd&1)*2], vh[dg][(ntd&1)*2+1]);
            }
        }
    }

    // ---------- denominators: quad butterfly on f32 partials, stage O ----------
    __syncthreads();   // QS region dead for everyone; OS may now be written
    #pragma unroll
    for (int mt = 0; mt < 2; mt++){
        float v0 = rs[mt][0], v1 = rs[mt][1];
        v0 += __shfl_xor_sync(0xffffffffu, v0, 1);
        v0 += __shfl_xor_sync(0xffffffffu, v0, 2);
        v1 += __shfl_xor_sync(0xffffffffu, v1, 1);
        v1 += __shfl_xor_sync(0xffffffffu, v1, 2);
        const float p0 = 1.f / v0;
        const float p1 = 1.f / v1;
        const int r0 = qbl + mt*16 + (lane >> 2);   // local row
        #pragma unroll
        for (int ntd = 0; ntd < 4; ntd++){
            const int cc = ntd*8 + 2*(lane & 3);
            float2 a, b2;
            a.x  = oAcc[mt][ntd][0] * p0;
            a.y  = oAcc[mt][ntd][1] * p0;
            b2.x = oAcc[mt][ntd][2] * p1;
            b2.y = oAcc[mt][ntd][3] * p1;
            *(float2*)(sm + OS_OFF + r0*144 + cc*4)      = a;
            *(float2*)(sm + OS_OFF + (r0+8)*144 + cc*4)  = b2;
        }
    }
    __syncthreads();

    // ---------- epilogue: 2x2-paired LePE conv + bias + store ----------
    {
        const int g  = tid >> 3;           // 0..31
        const int wp = (tid >> 2) & 1;     // 0..1
        const int c  = tid & 3;            // 0..3
        const int c0 = c * 8;
        const float* Wsm = (const float*)(sm + WS_OFF);
        const float* Bsm = (const float*)(sm + BS_OFF);

        float o[2][2][8];
        #pragma unroll
        for (int a = 0; a < 2; a++)
            #pragma unroll
            for (int b2 = 0; b2 < 2; b2++){
                const int r = (2*g + a)*4 + 2*wp + b2;
                uint32_t t0[4], t1[4];
                lds_v4(t0, smb + OS_OFF + (uint32_t)r*144u + (uint32_t)c0*4u);
                lds_v4(t1, smb + OS_OFF + (uint32_t)r*144u + (uint32_t)c0*4u + 16u);
                #pragma unroll
                for (int i = 0; i < 4; i++){
                    o[a][b2][i]   = __uint_as_float(t0[i]);
                    o[a][b2][4+i] = __uint_as_float(t1[i]);
                }
            }

        #pragma unroll
        for (int tt = 0; tt < 2; tt++){
            const int wtT = (tt - qhalf + 1) * 9;      // (dt+1)*9
            #pragma unroll
            for (int ho = -1; ho <= 2; ho++){          // hh = 2g + ho
                const int hh = 2*g + ho;
                if ((unsigned)hh >= 64u) continue;
                #pragma unroll
                for (int wo = -1; wo <= 2; wo++){      // ww = 2wp + wo
                    const int ww = 2*wp + wo;
                    if ((unsigned)ww >= 4u) continue;
                    const int n2 = tt*256 + hh*4 + ww;
                    uint32_t vp[4];
                    lds_v4(vp, smb + VH_OFF + (uint32_t)n2*80u + (uint32_t)c0*2u);
                    float x[8];
                    #pragma unroll
                    for (int i = 0; i < 4; i++){
                        const float2 f = __half22float2(*reinterpret_cast<const __half2*>(&vp[i]));
                        x[2*i] = f.x; x[2*i+1] = f.y;
                    }
                    #pragma unroll
                    for (int a = 0; a < 2; a++){
                        const int dh = ho - a;
                        if (dh < -1 || dh > 1) continue;
                        #pragma unroll
                        for (int b2 = 0; b2 < 2; b2++){
                            const int dw = wo - b2;
                            if (dw < -1 || dw > 1) continue;
                            const float* wr = Wsm + (wtT + (dh+1)*3 + (dw+1))*32 + c0;
                            #pragma unroll
                            for (int i = 0; i < 8; i++)
                                o[a][b2][i] += wr[i] * x[i];
                        }
                    }
                }
            }
        }

        #pragma unroll
        for (int a = 0; a < 2; a++)
            #pragma unroll
            for (int b2 = 0; b2 < 2; b2++){
                const int rh = 2*g + a, rws = 2*wp + b2;
                const size_t l = (size_t)(lbase + qhalf*4096 + rh*64 + rws);
                float* op = out + batch_off + l*Cc + chan + c0;
                float4 r4;
                r4.x = o[a][b2][0] + Bsm[c0+0];
                r4.y = o[a][b2][1] + Bsm[c0+1];
                r4.z = o[a][b2][2] + Bsm[c0+2];
                r4.w = o[a][b2][3] + Bsm[c0+3];
                ((float4*)op)[0] = r4;
                r4.x = o[a][b2][4] + Bsm[c0+4];
                r4.y = o[a][b2][5] + Bsm[c0+5];
                r4.z = o[a][b2][6] + Bsm[c0+6];
                r4.w = o[a][b2][7] + Bsm[c0+7];
                ((float4*)op)[1] = r4;
            }
    }
}

extern "C" void kernel_launch(void* const* d_in, const int* in_sizes, int n_in,
                              void* d_out, int out_size)
{
    const float* qkv = (const float*)d_in[0];
    const float* lw  = (const float*)d_in[1];
    const float* lb  = (const float*)d_in[2];
    float* out       = (float*)d_out;

    cudaFuncSetAttribute(lepe_hmma, cudaFuncAttributeMaxDynamicSharedMemorySize, SMEM_BYTES);
    lepe_hmma<<<1024, 256, SMEM_BYTES>>>(qkv, lw, lb, out);
}

// round 17
// speedup vs baseline: 1.0729x; 1.0729x over previous
#include <cuda_runtime.h>
#include <cuda_fp16.h>
#include <cstdint>

#define Bb 2
#define Ll 32768
#define Cc 128
#define NTOK 512
#define HD 32

// ---- smem byte offsets (per 256-thread CTA) ----
#define KF_OFF  0           // K fp16: 512 rows x 64B (swizzled)      32768
#define VH_OFF  32768       // V fp16 row-major: 512 rows x 80B       40960
#define OS_OFF  73728       // O fp32 [256][36] staging (also Q fp16 stage pre-mainloop)
#define QS_OFF  OS_OFF      //   Q fp16: 256 rows x 64B (swizzled)
#define WS_OFF  110592      // weights [27][32] f32                    3456
#define BS_OFF  114048      // bias [32] f32                            128
#define SMEM_BYTES 114176   // x2 CTAs/SM = 228352 <= 228KB

static __device__ __forceinline__ uint32_t s2u(const void* p){
    uint32_t a;
    asm("{ .reg .u64 t; cvta.to.shared.u64 t, %1; cvt.u32.u64 %0, t; }" : "=r"(a) : "l"(p));
    return a;
}
static __device__ __forceinline__ uint32_t pk2h(float a, float b){
    uint32_t r; asm("cvt.rn.f16x2.f32 %0, %1, %2;" : "=r"(r) : "f"(b), "f"(a)); return r;
}
static __device__ __forceinline__ uint32_t ex2h2(uint32_t a){
    uint32_t r; asm("ex2.approx.f16x2 %0, %1;" : "=r"(r) : "r"(a)); return r;
}
static __device__ __forceinline__ void ldm4(uint32_t* r, uint32_t a){
    asm volatile("ldmatrix.sync.aligned.m8n8.x4.shared.b16 {%0,%1,%2,%3}, [%4];"
        : "=r"(r[0]), "=r"(r[1]), "=r"(r[2]), "=r"(r[3]) : "r"(a));
}
static __device__ __forceinline__ void ldm4t(uint32_t* r, uint32_t a){
    asm volatile("ldmatrix.sync.aligned.m8n8.x4.trans.shared.b16 {%0,%1,%2,%3}, [%4];"
        : "=r"(r[0]), "=r"(r[1]), "=r"(r[2]), "=r"(r[3]) : "r"(a));
}
// fp32-accumulate MMA (PV path + row-sum)
static __device__ __forceinline__ void mma16816(float* d, const uint32_t* a, uint32_t b0, uint32_t b1){
    asm volatile("mma.sync.aligned.m16n8k16.row.col.f32.f16.f16.f32 "
        "{%0,%1,%2,%3},{%4,%5,%6,%7},{%8,%9},{%0,%1,%2,%3};"
        : "+f"(d[0]), "+f"(d[1]), "+f"(d[2]), "+f"(d[3])
        : "r"(a[0]), "r"(a[1]), "r"(a[2]), "r"(a[3]), "r"(b0), "r"(b1));
}
// fp16-accumulate MMA (QK path): D/C are 2x f16x2 regs
static __device__ __forceinline__ void mma16816h(uint32_t* d, const uint32_t* a, uint32_t b0, uint32_t b1){
    asm volatile("mma.sync.aligned.m16n8k16.row.col.f16.f16.f16.f16 "
        "{%0,%1},{%2,%3,%4,%5},{%6,%7},{%0,%1};"
        : "+r"(d[0]), "+r"(d[1])
        : "r"(a[0]), "r"(a[1]), "r"(a[2]), "r"(a[3]), "r"(b0), "r"(b1));
}
static __device__ __forceinline__ void sts_v4(uint32_t a, uint32_t x, uint32_t y, uint32_t z, uint32_t w){
    asm volatile("st.shared.v4.b32 [%0], {%1,%2,%3,%4};" :: "r"(a), "r"(x), "r"(y), "r"(z), "r"(w) : "memory");
}
static __device__ __forceinline__ void lds_v4(uint32_t* r, uint32_t a){
    asm volatile("ld.shared.v4.b32 {%0,%1,%2,%3}, [%4];"
        : "=r"(r[0]), "=r"(r[1]), "=r"(r[2]), "=r"(r[3]) : "r"(a));
}
// 64B rows; 16B-chunk c rotated by (row>>1) -> conflict-free ldmatrix (used for K and Q)
static __device__ __forceinline__ uint32_t kaddr(int n, int c){
    return (uint32_t)n*64u + ((((uint32_t)c + ((uint32_t)n >> 1)) & 3u) * 16u);
}

__global__ void __launch_bounds__(256, 2)
lepe_hmma(const float* __restrict__ qkv,
          const float* __restrict__ lw,
          const float* __restrict__ lb,
          float* __restrict__ out)
{
    extern __shared__ char sm[];
    const uint32_t smb = s2u(sm);
    const int tid = threadIdx.x;
    const int wid = tid >> 5, lane = tid & 31;

    const int bx = blockIdx.x;            // (window, head, qhalf)
    const int win = bx >> 3, head = (bx >> 1) & 3, qhalf = bx & 1;
    const int b  = win >> 6;
    const int tB = (win >> 4) & 3;
    const int wB = win & 15;
    const size_t batch_off = (size_t)b * Ll * Cc;
    const int chan  = head * HD;
    const int lbase = tB*8192 + wB*4;

    const float* qg = qkv + batch_off;
    const float* kg = qkv + (size_t)1*Bb*Ll*Cc + batch_off;
    const float* vg = qkv + (size_t)2*Bb*Ll*Cc + batch_off;

    // ---------- stage K fp16 (swizzled), V fp16 row-major, Q fp16 (swizzled, scaled) ----------
    {
        const int q = tid & 3;            // 4 threads per row, 8 d-values each
        const int rbase = tid >> 2;       // 0..63
        #pragma unroll
        for (int it = 0; it < 8; it++){
            const int j = it*64 + rbase;
            const int t = j >> 8, h = (j >> 2) & 63, ws = j & 3;
            const size_t l = (size_t)(lbase + t*4096 + h*64 + ws);
            const float4 k0 = *(const float4*)(kg + l*Cc + chan + q*8);
            const float4 k1 = *(const float4*)(kg + l*Cc + chan + q*8 + 4);
            sts_v4(smb + KF_OFF + kaddr(j, q),
                   pk2h(k0.x, k0.y), pk2h(k0.z, k0.w),
                   pk2h(k1.x, k1.y), pk2h(k1.z, k1.w));

            const float4 v0 = *(const float4*)(vg + l*Cc + chan + q*8);
            const float4 v1 = *(const float4*)(vg + l*Cc + chan + q*8 + 4);
            sts_v4(smb + VH_OFF + (uint32_t)j*80u + (uint32_t)q*16u,
                   pk2h(v0.x, v0.y), pk2h(v0.z, v0.w),
                   pk2h(v1.x, v1.y), pk2h(v1.z, v1.w));
            if (q == 3)   // pad: d32 = 1.0 (tensor row-sum column), rest 0
                sts_v4(smb + VH_OFF + (uint32_t)j*80u + 64u, 0x00003C00u, 0u, 0u, 0u);
        }
        // Q: 256 local rows (this qhalf), scaled into log2 domain
        const float sc = 0.17677669529663689f * 1.4426950408889634f;
        #pragma unroll
        for (int it = 0; it < 4; it++){
            const int rl = it*64 + rbase;                 // local q-row 0..255
            const int r  = qhalf*256 + rl;                // global in-window row
            const int t = r >> 8, h = (r >> 2) & 63, ws = r & 3;
            const size_t l = (size_t)(lbase + t*4096 + h*64 + ws);
            const float4 q0 = *(const float4*)(qg + l*Cc + chan + q*8);
            const float4 q1 = *(const float4*)(qg + l*Cc + chan + q*8 + 4);
            sts_v4(smb + QS_OFF + kaddr(rl, q),
                   pk2h(q0.x*sc, q0.y*sc), pk2h(q0.z*sc, q0.w*sc),
                   pk2h(q1.x*sc, q1.y*sc), pk2h(q1.z*sc, q1.w*sc));
        }
        for (int idx = tid; idx < 27*32; idx += 256){
            const int tap = idx >> 5, d = idx & 31;
            ((float*)(sm + WS_OFF))[tap*32 + d] = lw[(chan + d)*27 + tap];
        }
        if (tid < 32) ((float*)(sm + BS_OFF))[tid] = lb[chan + tid];
    }
    __syncthreads();

    // ---------- Q fragments via ldmatrix from smem ----------
    const int qbl = wid*32;               // local (within-CTA) row base for this warp
    uint32_t qf[2][2][4];
    {
        const int row_off = (lane & 7) + ((lane >> 3) & 1)*8;
        const int ch_base = (lane >> 4);  // 0 or 1
        #pragma unroll
        for (int mt = 0; mt < 2; mt++)
            #pragma unroll
            for (int kt = 0; kt < 2; kt++)
                ldm4(qf[mt][kt], smb + QS_OFF + kaddr(qbl + mt*16 + row_off, ch_base + kt*2));
    }

    // ---------- mainloop: 32 subchunks of 16 keys ----------
    float oAcc[2][4][4];
    #pragma unroll
    for (int a = 0; a < 2; a++)
        #pragma unroll
        for (int b2 = 0; b2 < 4; b2++)
            #pragma unroll
            for (int c = 0; c < 4; c++) oAcc[a][b2][c] = 0.f;
    float oSum[2][4];
    #pragma unroll
    for (int a = 0; a < 2; a++)
        #pragma unroll
        for (int c = 0; c < 4; c++) oSum[a][c] = 0.f;

    const int lg = lane >> 3, lr = lane & 7;
    // ones B-fragment (B[k][0]=1, else 0) as compile-time constant
    const uint32_t vs2c = (lane < 4) ? 0x3C003C00u : 0u;

    #pragma unroll 1
    for (int cs = 0; cs < 32; cs++){
        const int j0 = cs * 16;
        // K fragments (B operand for QK)
        uint32_t kh[2][4];
        #pragma unroll
        for (int nt = 0; nt < 2; nt++)
            ldm4(kh[nt], smb + KF_OFF + kaddr(j0 + nt*8 + lr, lg));
        // V fragments via ldmatrix.trans from row-major fp16 V
        uint32_t vh[2][4];
        #pragma unroll
        for (int dg = 0; dg < 2; dg++){
            const uint32_t a = smb + VH_OFF
                + (uint32_t)(j0 + (lg & 1)*8 + lr)*80u
                + (uint32_t)dg*32u + (uint32_t)(lg >> 1)*16u;
            ldm4t(vh[dg], a);
        }
        // S = Q K^T, fp16 accumulate: D regs are already PV A-fragment packed
        uint32_t sh[2][2][2];
        #pragma unroll
        for (int mt = 0; mt < 2; mt++)
            #pragma unroll
            for (int nt = 0; nt < 2; nt++){
                uint32_t* sd = sh[mt][nt];
                sd[0] = 0u; sd[1] = 0u;
                mma16816h(sd, qf[mt][0], kh[nt][0], kh[nt][1]);
                mma16816h(sd, qf[mt][1], kh[nt][2], kh[nt][3]);
            }
        // softmax: ex2.f16x2 straight on the MMA output + PV + tensor row-sum
        #pragma unroll
        for (int mt = 0; mt < 2; mt++){
            uint32_t ah[4];
            ah[0] = ex2h2(sh[mt][0][0]);   // row r,   keys 2c,2c+1 (nt0)
            ah[1] = ex2h2(sh[mt][0][1]);   // row r+8, keys 2c,2c+1 (nt0)
            ah[2] = ex2h2(sh[mt][1][0]);   // row r,   keys 8+2c   (nt1)
            ah[3] = ex2h2(sh[mt][1][1]);   // row r+8, keys 8+2c   (nt1)
            #pragma unroll
            for (int ntd = 0; ntd < 4; ntd++){
                const int dg = ntd >> 1;
                mma16816(oAcc[mt][ntd], ah, vh[dg][(ntd&1)*2], vh[dg][(ntd&1)*2+1]);
            }
            mma16816(oSum[mt], ah, vs2c, vs2c);   // col n=0 = Sum(p)
        }
    }

    // ---------- denominators (col 0 on lanes lane&3==0), stage O ----------
    __syncthreads();   // QS region dead for everyone; OS may now be written
    #pragma unroll
    for (int mt = 0; mt < 2; mt++){
        const float d0 = __shfl_sync(0xffffffffu, oSum[mt][0], lane & ~3);
        const float d1 = __shfl_sync(0xffffffffu, oSum[mt][2], lane & ~3);
        const float p0 = 1.f / d0;
        const float p1 = 1.f / d1;
        const int r0 = qbl + mt*16 + (lane >> 2);   // local row
        #pragma unroll
        for (int ntd = 0; ntd < 4; ntd++){
            const int cc = ntd*8 + 2*(lane & 3);
            float2 a, b2;
            a.x  = oAcc[mt][ntd][0] * p0;
            a.y  = oAcc[mt][ntd][1] * p0;
            b2.x = oAcc[mt][ntd][2] * p1;
            b2.y = oAcc[mt][ntd][3] * p1;
            *(float2*)(sm + OS_OFF + r0*144 + cc*4)      = a;
            *(float2*)(sm + OS_OFF + (r0+8)*144 + cc*4)  = b2;
        }
    }
    __syncthreads();

    // ---------- epilogue: 2x2-paired LePE conv + bias + store ----------
    {
        const int g  = tid >> 3;           // 0..31
        const int wp = (tid >> 2) & 1;     // 0..1
        const int c  = tid & 3;            // 0..3
        const int c0 = c * 8;
        const float* Wsm = (const float*)(sm + WS_OFF);
        const float* Bsm = (const float*)(sm + BS_OFF);

        float o[2][2][8];
        #pragma unroll
        for (int a = 0; a < 2; a++)
            #pragma unroll
            for (int b2 = 0; b2 < 2; b2++){
                const int r = (2*g + a)*4 + 2*wp + b2;
                uint32_t t0[4], t1[4];
                lds_v4(t0, smb + OS_OFF + (uint32_t)r*144u + (uint32_t)c0*4u);
                lds_v4(t1, smb + OS_OFF + (uint32_t)r*144u + (uint32_t)c0*4u + 16u);
                #pragma unroll
                for (int i = 0; i < 4; i++){
                    o[a][b2][i]   = __uint_as_float(t0[i]);
                    o[a][b2][4+i] = __uint_as_float(t1[i]);
                }
            }

        #pragma unroll
        for (int tt = 0; tt < 2; tt++){
            const int wtT = (tt - qhalf + 1) * 9;      // (dt+1)*9
            #pragma unroll
            for (int ho = -1; ho <= 2; ho++){          // hh = 2g + ho
                const int hh = 2*g + ho;
                if ((unsigned)hh >= 64u) continue;
                #pragma unroll
                for (int wo = -1; wo <= 2; wo++){      // ww = 2wp + wo
                    const int ww = 2*wp + wo;
                    if ((unsigned)ww >= 4u) continue;
                    const int n2 = tt*256 + hh*4 + ww;
                    uint32_t vp[4];
                    lds_v4(vp, smb + VH_OFF + (uint32_t)n2*80u + (uint32_t)c0*2u);
                    float x[8];
                    #pragma unroll
                    for (int i = 0; i < 4; i++){
                        const float2 f = __half22float2(*reinterpret_cast<const __half2*>(&vp[i]));
                        x[2*i] = f.x; x[2*i+1] = f.y;
                    }
                    #pragma unroll
                    for (int a = 0; a < 2; a++){
                        const int dh = ho - a;
                        if (dh < -1 || dh > 1) continue;
                        #pragma unroll
                        for (int b2 = 0; b2 < 2; b2++){
                            const int dw = wo - b2;
                            if (dw < -1 || dw > 1) continue;
                            const float* wr = Wsm + (wtT + (dh+1)*3 + (dw+1))*32 + c0;
                            #pragma unroll
                            for (int i = 0; i < 8; i++)
                                o[a][b2][i] += wr[i] * x[i];
                        }
                    }
                }
            }
        }

        #pragma unroll
        for (int a = 0; a < 2; a++)
            #pragma unroll
            for (int b2 = 0; b2 < 2; b2++){
                const int rh = 2*g + a, rws = 2*wp + b2;
                const size_t l = (size_t)(lbase + qhalf*4096 + rh*64 + rws);
                float* op = out + batch_off + l*Cc + chan + c0;
                float4 r4;
                r4.x = o[a][b2][0] + Bsm[c0+0];
                r4.y = o[a][b2][1] + Bsm[c0+1];
                r4.z = o[a][b2][2] + Bsm[c0+2];
                r4.w = o[a][b2][3] + Bsm[c0+3];
                ((float4*)op)[0] = r4;
                r4.x = o[a][b2][4] + Bsm[c0+4];
                r4.y = o[a][b2][5] + Bsm[c0+5];
                r4.z = o[a][b2][6] + Bsm[c0+6];
                r4.w = o[a][b2][7] + Bsm[c0+7];
                ((float4*)op)[1] = r4;
            }
    }
}

extern "C" void kernel_launch(void* const* d_in, const int* in_sizes, int n_in,
                              void* d_out, int out_size)
{
    const float* qkv = (const float*)d_in[0];
    const float* lw  = (const float*)d_in[1];
    const float* lb  = (const float*)d_in[2];
    float* out       = (float*)d_out;

    cudaFuncSetAttribute(lepe_hmma, cudaFuncAttributeMaxDynamicSharedMemorySize, SMEM_BYTES);
    lepe_hmma<<<1024, 256, SMEM_BYTES>>>(qkv, lw, lb, out);
}